// round 13
// baseline (speedup 1.0000x reference)
#include <cuda_runtime.h>
#include <cuda_bf16.h>
#include <math.h>
#include <stdint.h>

#define V_NUM 4
#define B_SZ  2048
#define D_DIM 512
#define N_ROWS 8192
#define NTILES 2080
// xn scaled by sqrt(2*log2(e)) so acc = sim2 * log2(e): exp(sim2)=ex2(acc).
#define SCALE_SIDE 1.6986436f
#define LN2F 0.69314718055994531f

__device__ __nv_bfloat16 g_xn[(size_t)N_ROWS * D_DIM];
__device__ float g_rowsum[N_ROWS];
__device__ float g_pos[V_NUM * V_NUM * B_SZ];
__device__ unsigned int g_done;

// ---------------------------------------------------------------------------
// Normalize (warp per row) -> bf16 (exp-scale folded), fused zeroing.
// ---------------------------------------------------------------------------
__global__ void normalize_kernel(const float* __restrict__ x,
                                 float* __restrict__ out) {
    const int lane = threadIdx.x & 31;
    const int row = blockIdx.x * 8 + (threadIdx.x >> 5);
    const float4* xr = (const float4*)(x + (size_t)row * D_DIM);
    float4 v[4];
    float ss = 0.0f;
    #pragma unroll
    for (int q = 0; q < 4; q++) {
        v[q] = xr[lane + 32 * q];
        ss = fmaf(v[q].x, v[q].x, ss);
        ss = fmaf(v[q].y, v[q].y, ss);
        ss = fmaf(v[q].z, v[q].z, ss);
        ss = fmaf(v[q].w, v[q].w, ss);
    }
    #pragma unroll
    for (int o = 16; o > 0; o >>= 1) ss += __shfl_xor_sync(0xFFFFFFFFu, ss, o);
    const float inv = SCALE_SIDE / fmaxf(sqrtf(ss), 1e-8f);
    uint2* dst = (uint2*)(g_xn + (size_t)row * D_DIM);
    #pragma unroll
    for (int q = 0; q < 4; q++) {
        __nv_bfloat162 h0 = __floats2bfloat162_rn(v[q].x * inv, v[q].y * inv);
        __nv_bfloat162 h1 = __floats2bfloat162_rn(v[q].z * inv, v[q].w * inv);
        uint2 pk;
        pk.x = *(uint32_t*)&h0;
        pk.y = *(uint32_t*)&h1;
        dst[lane + 32 * q] = pk;
    }
    if (lane == 0) g_rowsum[row] = 0.0f;
    if (row == 0 && lane == 0) { out[0] = 0.0f; g_done = 0u; }
}

// ---------------------------------------------------------------------------
// bf16 mma.sync fused kernel.  Flat triangular grid over 64x64 upper tiles.
// Tile 128x128, K=512 in 8 chunks of 64 (128B/row, SW128).  3-stage cp.async
// ring, one __syncthreads per chunk, FULLY UNROLLED (static ring slots).
// 8 warps (4x2), warp tile 32x64 = 2 x 8 m16n8k16 mma.  Epilogue: ex2 direct
// on acc, row/col exp-sums (symmetry), positives from tile diagonals.
// Last block (done-counter) computes the final scalar loss.
// ---------------------------------------------------------------------------
#define STAGE_BYTES 32768
#define SMEM_MAIN (3 * STAGE_BYTES)
#define SIMEXP_SMEM (SMEM_MAIN + 1024)

__device__ __forceinline__ void cp16(uint32_t s, const void* g) {
    asm volatile("cp.async.cg.shared.global [%0], [%1], 16;\n" :: "r"(s), "l"(g));
}

__global__ __launch_bounds__(256, 2)
void simexp_kernel(float* __restrict__ out) {
    // --- flat triangular block index -> (by, bx), bx >= by
    const int t = blockIdx.x;
    int by = (int)((129.0f - sqrtf(16641.0f - 8.0f * (float)t)) * 0.5f);
    if (by > 63) by = 63;
    while (64 * by - (by * (by - 1)) / 2 > t) by--;
    while (64 * (by + 1) - ((by + 1) * by) / 2 <= t) by++;
    const int bx = by + (t - (64 * by - (by * (by - 1)) / 2));

    extern __shared__ char smem[];
    const uint32_t smemU = (uint32_t)__cvta_generic_to_shared(smem);
    const int tid = threadIdx.x;
    const int lane = tid & 31;
    const int wid = tid >> 5;
    const int wm = wid >> 1;
    const int wn = wid & 1;
    const int rowBase = by << 7, colBase = bx << 7;

    float* s_rsum = (float*)(smem + SMEM_MAIN);
    float* s_csum = s_rsum + 128;
    if (tid < 128) { s_rsum[tid] = 0.0f; s_csum[tid] = 0.0f; }

    float acc[2][8][4];
    #pragma unroll
    for (int mi = 0; mi < 2; mi++)
        #pragma unroll
        for (int ni = 0; ni < 8; ni++)
            #pragma unroll
            for (int e = 0; e < 4; e++) acc[mi][ni][e] = 0.0f;

    // --- loaders (SW128 swizzle: 16B-chunk' = chunk ^ (row & 7))
    const int lr = tid >> 3;
    const int lc = tid & 7;
    const uint32_t swzCol = (uint32_t)((lc ^ (lr & 7)) << 4);
    const char* gbase = (const char*)g_xn;

    auto load_chunk = [&](int ck, int slot) {
        uint32_t sb = smemU + (uint32_t)slot * STAGE_BYTES;
        #pragma unroll
        for (int tp = 0; tp < 2; tp++) {
            const int rb = tp ? colBase : rowBase;
            const uint32_t sbb = sb + tp * 16384;
            #pragma unroll
            for (int u = 0; u < 4; u++) {
                int r = lr + 32 * u;
                cp16(sbb + (uint32_t)(r * 128) + swzCol,
                     gbase + (size_t)(rb + r) * (D_DIM * 2) + ck * 128 + lc * 16);
            }
        }
        asm volatile("cp.async.commit_group;\n" ::);
    };

    const int rA0 = wm * 32 + (lane & 15);
    const int nB0 = wn * 64 + ((lane >> 4) << 3) + (lane & 7);
    const int laneSw = lane & 7;

    auto compute_chunk = [&](int slot) {
        const uint32_t sA = smemU + (uint32_t)slot * STAGE_BYTES;
        const uint32_t sB = sA + 16384;
        #pragma unroll
        for (int kk = 0; kk < 4; kk++) {
            uint32_t a[2][4];
            const uint32_t chA = (uint32_t)(((kk * 2 + (lane >> 4)) ^ laneSw) << 4);
            #pragma unroll
            for (int m2 = 0; m2 < 2; m2++) {
                uint32_t addr = sA + (uint32_t)((rA0 + m2 * 16) * 128) + chA;
                asm volatile("ldmatrix.sync.aligned.m8n8.x4.shared.b16 {%0,%1,%2,%3}, [%4];"
                    : "=r"(a[m2][0]), "=r"(a[m2][1]), "=r"(a[m2][2]), "=r"(a[m2][3])
                    : "r"(addr));
            }
            uint32_t b[4][4];
            const uint32_t chB = (uint32_t)(((kk * 2 + ((lane >> 3) & 1)) ^ laneSw) << 4);
            #pragma unroll
            for (int g = 0; g < 4; g++) {
                uint32_t addr = sB + (uint32_t)((nB0 + g * 16) * 128) + chB;
                asm volatile("ldmatrix.sync.aligned.m8n8.x4.shared.b16 {%0,%1,%2,%3}, [%4];"
                    : "=r"(b[g][0]), "=r"(b[g][1]), "=r"(b[g][2]), "=r"(b[g][3])
                    : "r"(addr));
            }
            #pragma unroll
            for (int mi = 0; mi < 2; mi++)
                #pragma unroll
                for (int ni = 0; ni < 8; ni++) {
                    uint32_t b0 = b[ni >> 1][(ni & 1) * 2];
                    uint32_t b1 = b[ni >> 1][(ni & 1) * 2 + 1];
                    asm volatile(
                        "mma.sync.aligned.m16n8k16.row.col.f32.bf16.bf16.f32 "
                        "{%0,%1,%2,%3}, {%4,%5,%6,%7}, {%8,%9}, {%0,%1,%2,%3};"
                        : "+f"(acc[mi][ni][0]), "+f"(acc[mi][ni][1]),
                          "+f"(acc[mi][ni][2]), "+f"(acc[mi][ni][3])
                        : "r"(a[mi][0]), "r"(a[mi][1]), "r"(a[mi][2]), "r"(a[mi][3]),
                          "r"(b0), "r"(b1));
                }
        }
    };

    // --- mainloop: 8 chunks, 3-stage ring, fully unrolled (static slots)
    load_chunk(0, 0);
    load_chunk(1, 1);
    #pragma unroll
    for (int it = 0; it < 8; it++) {
        if (it < 7) asm volatile("cp.async.wait_group 1;\n" ::);
        else        asm volatile("cp.async.wait_group 0;\n" ::);
        __syncthreads();
        if (it + 2 < 8) load_chunk(it + 2, (it + 2) % 3);
        compute_chunk(it % 3);
    }

    // --- epilogue: ex2 direct (scale folded into data), sums, positives
    const bool posTile = ((bx - by) & 15) == 0;
    float rowp[2][2] = {{0.f, 0.f}, {0.f, 0.f}};
    float colp[8][2];
    #pragma unroll
    for (int ni = 0; ni < 8; ni++) { colp[ni][0] = 0.f; colp[ni][1] = 0.f; }

    #pragma unroll
    for (int mi = 0; mi < 2; mi++)
        #pragma unroll
        for (int ni = 0; ni < 8; ni++)
            #pragma unroll
            for (int e = 0; e < 4; e++) {
                float ev;
                asm("ex2.approx.f32 %0, %1;" : "=f"(ev) : "f"(acc[mi][ni][e]));
                rowp[mi][e >> 1] += ev;
                colp[ni][e & 1] += ev;
                if (posTile) {
                    int rl = wm * 32 + mi * 16 + (e >> 1) * 8 + (lane >> 2);
                    int cl = wn * 64 + ni * 8 + (lane & 3) * 2 + (e & 1);
                    if (rl == cl) {
                        int gr = rowBase + rl, gc = colBase + cl;
                        g_pos[((gr >> 11) * V_NUM + (gc >> 11)) * B_SZ + (gr & 2047)] =
                            acc[mi][ni][e] * LN2F;
                    }
                }
            }

    #pragma unroll
    for (int mi = 0; mi < 2; mi++)
        #pragma unroll
        for (int rh = 0; rh < 2; rh++) {
            float s = rowp[mi][rh];
            s += __shfl_xor_sync(0xFFFFFFFFu, s, 1);
            s += __shfl_xor_sync(0xFFFFFFFFu, s, 2);
            if ((lane & 3) == 0)
                atomicAdd(&s_rsum[wm * 32 + mi * 16 + rh * 8 + (lane >> 2)], s);
        }
    #pragma unroll
    for (int ni = 0; ni < 8; ni++)
        #pragma unroll
        for (int e01 = 0; e01 < 2; e01++) {
            float s = colp[ni][e01];
            s += __shfl_xor_sync(0xFFFFFFFFu, s, 4);
            s += __shfl_xor_sync(0xFFFFFFFFu, s, 8);
            s += __shfl_xor_sync(0xFFFFFFFFu, s, 16);
            if (lane < 4)
                atomicAdd(&s_csum[wn * 64 + ni * 8 + lane * 2 + e01], s);
        }
    __syncthreads();
    if (tid < 128) {
        atomicAdd(&g_rowsum[rowBase + tid], s_rsum[tid]);
    } else if (bx != by) {
        atomicAdd(&g_rowsum[colBase + tid - 128], s_csum[tid - 128]);
    }

    // --- completion counter; last block computes the loss
    __shared__ unsigned int s_rank;
    __threadfence();
    __syncthreads();
    if (tid == 0) s_rank = atomicAdd(&g_done, 1u);
    __syncthreads();
    if (s_rank == NTILES - 1) {
        __threadfence();
        float L = 0.0f;
        for (int r = tid; r < N_ROWS; r += 256) {
            const int i = r >> 11, b = r & 2047;
            float p[V_NUM];
            #pragma unroll
            for (int j = 0; j < V_NUM; j++) {
                int lo = i < j ? i : j;
                int hi = i < j ? j : i;
                p[j] = g_pos[(lo * V_NUM + hi) * B_SZ + b];
            }
            float S = g_rowsum[r];
            #pragma unroll
            for (int j = 0; j < V_NUM; j++) S -= __expf(p[j]);
            #pragma unroll
            for (int j = 0; j < V_NUM; j++)
                if (j != i) L += log1pf(S * __expf(-p[j]));
        }
        L *= (1.0f / (float)B_SZ);
        #pragma unroll
        for (int o = 16; o > 0; o >>= 1) L += __shfl_xor_sync(0xFFFFFFFFu, L, o);
        float* ws = s_rsum;
        if ((tid & 31) == 0) ws[tid >> 5] = L;
        __syncthreads();
        if (tid == 0) {
            float s = 0.0f;
            #pragma unroll
            for (int w = 0; w < 8; w++) s += ws[w];
            out[0] = s;
        }
    }
}

// ---------------------------------------------------------------------------
extern "C" void kernel_launch(void* const* d_in, const int* in_sizes, int n_in,
                              void* d_out, int out_size) {
    const float* x = (const float*)d_in[0];
    float* out = (float*)d_out;

    cudaFuncSetAttribute(simexp_kernel,
                         cudaFuncAttributeMaxDynamicSharedMemorySize, SIMEXP_SMEM);

    normalize_kernel<<<N_ROWS / 8, 256>>>(x, out);
    simexp_kernel<<<NTILES, 256, SIMEXP_SMEM>>>(out);
}

// round 14
// speedup vs baseline: 1.3819x; 1.3819x over previous
#include <cuda_runtime.h>
#include <cuda_bf16.h>
#include <math.h>
#include <stdint.h>

#define V_NUM 4
#define B_SZ  2048
#define D_DIM 512
#define N_ROWS 8192
#define NTILES 2080
// xn scaled by sqrt(2*log2(e)) so acc = sim2 * log2(e): exp(sim2)=ex2(acc).
#define SCALE_SIDE 1.6986436f
#define LN2F 0.69314718055994531f

__device__ __nv_bfloat16 g_xn[(size_t)N_ROWS * D_DIM];
__device__ float g_rowsum[N_ROWS];
__device__ float g_pos[V_NUM * V_NUM * B_SZ];

// ---------------------------------------------------------------------------
// Normalize (warp per row) -> bf16 (exp-scale folded), fused zeroing.
// ---------------------------------------------------------------------------
__global__ void normalize_kernel(const float* __restrict__ x,
                                 float* __restrict__ out) {
    const int lane = threadIdx.x & 31;
    const int row = blockIdx.x * 8 + (threadIdx.x >> 5);
    const float4* xr = (const float4*)(x + (size_t)row * D_DIM);
    float4 v[4];
    float ss = 0.0f;
    #pragma unroll
    for (int q = 0; q < 4; q++) {
        v[q] = xr[lane + 32 * q];
        ss = fmaf(v[q].x, v[q].x, ss);
        ss = fmaf(v[q].y, v[q].y, ss);
        ss = fmaf(v[q].z, v[q].z, ss);
        ss = fmaf(v[q].w, v[q].w, ss);
    }
    #pragma unroll
    for (int o = 16; o > 0; o >>= 1) ss += __shfl_xor_sync(0xFFFFFFFFu, ss, o);
    const float inv = SCALE_SIDE / fmaxf(sqrtf(ss), 1e-8f);
    uint2* dst = (uint2*)(g_xn + (size_t)row * D_DIM);
    #pragma unroll
    for (int q = 0; q < 4; q++) {
        __nv_bfloat162 h0 = __floats2bfloat162_rn(v[q].x * inv, v[q].y * inv);
        __nv_bfloat162 h1 = __floats2bfloat162_rn(v[q].z * inv, v[q].w * inv);
        uint2 pk;
        pk.x = *(uint32_t*)&h0;
        pk.y = *(uint32_t*)&h1;
        dst[lane + 32 * q] = pk;
    }
    if (lane == 0) g_rowsum[row] = 0.0f;
    if (row == 0 && lane == 0) out[0] = 0.0f;
}

// ---------------------------------------------------------------------------
// bf16 mma.sync fused kernel.  Flat triangular grid over 64x64 upper tiles.
// Tile 128x128, K=512 in 8 chunks of 64 (128B/row, SW128).  3-stage cp.async
// ring, one __syncthreads per chunk.  8 warps (4x2), warp tile 32x64 =
// 2 x 8 m16n8k16 mma.  Epilogue: ex2 on acc, warp-shuffle reductions, then
// DIRECT global atomics (no smem staging, no extra barriers).
// ---------------------------------------------------------------------------
#define STAGE_BYTES 32768
#define SIMEXP_SMEM (3 * STAGE_BYTES)

__device__ __forceinline__ void cp16(uint32_t s, const void* g) {
    asm volatile("cp.async.cg.shared.global [%0], [%1], 16;\n" :: "r"(s), "l"(g));
}

__global__ __launch_bounds__(256, 2)
void simexp_kernel() {
    // --- flat triangular block index -> (by, bx), bx >= by
    const int t = blockIdx.x;
    int by = (int)((129.0f - sqrtf(16641.0f - 8.0f * (float)t)) * 0.5f);
    if (by > 63) by = 63;
    while (64 * by - (by * (by - 1)) / 2 > t) by--;
    while (64 * (by + 1) - ((by + 1) * by) / 2 <= t) by++;
    const int bx = by + (t - (64 * by - (by * (by - 1)) / 2));

    extern __shared__ char smem[];
    const uint32_t smemU = (uint32_t)__cvta_generic_to_shared(smem);
    const int tid = threadIdx.x;
    const int lane = tid & 31;
    const int wid = tid >> 5;
    const int wm = wid >> 1;
    const int wn = wid & 1;
    const int rowBase = by << 7, colBase = bx << 7;

    float acc[2][8][4];
    #pragma unroll
    for (int mi = 0; mi < 2; mi++)
        #pragma unroll
        for (int ni = 0; ni < 8; ni++)
            #pragma unroll
            for (int e = 0; e < 4; e++) acc[mi][ni][e] = 0.0f;

    // --- loaders (SW128 swizzle: 16B-chunk' = chunk ^ (row & 7))
    const int lr = tid >> 3;
    const int lc = tid & 7;
    const uint32_t swzCol = (uint32_t)((lc ^ (lr & 7)) << 4);
    const char* gbase = (const char*)g_xn;

    auto load_chunk = [&](int ck) {
        uint32_t sb = smemU + (uint32_t)(ck % 3) * STAGE_BYTES;
        #pragma unroll
        for (int tp = 0; tp < 2; tp++) {
            const int rb = tp ? colBase : rowBase;
            const uint32_t sbb = sb + tp * 16384;
            #pragma unroll
            for (int u = 0; u < 4; u++) {
                int r = lr + 32 * u;
                cp16(sbb + (uint32_t)(r * 128) + swzCol,
                     gbase + (size_t)(rb + r) * (D_DIM * 2) + ck * 128 + lc * 16);
            }
        }
        asm volatile("cp.async.commit_group;\n" ::);
    };

    const int rA0 = wm * 32 + (lane & 15);
    const int nB0 = wn * 64 + ((lane >> 4) << 3) + (lane & 7);
    const int laneSw = lane & 7;

    auto compute_chunk = [&](int ck) {
        const uint32_t sA = smemU + (uint32_t)(ck % 3) * STAGE_BYTES;
        const uint32_t sB = sA + 16384;
        #pragma unroll
        for (int kk = 0; kk < 4; kk++) {
            uint32_t a[2][4];
            const uint32_t chA = (uint32_t)(((kk * 2 + (lane >> 4)) ^ laneSw) << 4);
            #pragma unroll
            for (int m2 = 0; m2 < 2; m2++) {
                uint32_t addr = sA + (uint32_t)((rA0 + m2 * 16) * 128) + chA;
                asm volatile("ldmatrix.sync.aligned.m8n8.x4.shared.b16 {%0,%1,%2,%3}, [%4];"
                    : "=r"(a[m2][0]), "=r"(a[m2][1]), "=r"(a[m2][2]), "=r"(a[m2][3])
                    : "r"(addr));
            }
            uint32_t b[4][4];
            const uint32_t chB = (uint32_t)(((kk * 2 + ((lane >> 3) & 1)) ^ laneSw) << 4);
            #pragma unroll
            for (int g = 0; g < 4; g++) {
                uint32_t addr = sB + (uint32_t)((nB0 + g * 16) * 128) + chB;
                asm volatile("ldmatrix.sync.aligned.m8n8.x4.shared.b16 {%0,%1,%2,%3}, [%4];"
                    : "=r"(b[g][0]), "=r"(b[g][1]), "=r"(b[g][2]), "=r"(b[g][3])
                    : "r"(addr));
            }
            #pragma unroll
            for (int mi = 0; mi < 2; mi++)
                #pragma unroll
                for (int ni = 0; ni < 8; ni++) {
                    uint32_t b0 = b[ni >> 1][(ni & 1) * 2];
                    uint32_t b1 = b[ni >> 1][(ni & 1) * 2 + 1];
                    asm volatile(
                        "mma.sync.aligned.m16n8k16.row.col.f32.bf16.bf16.f32 "
                        "{%0,%1,%2,%3}, {%4,%5,%6,%7}, {%8,%9}, {%0,%1,%2,%3};"
                        : "+f"(acc[mi][ni][0]), "+f"(acc[mi][ni][1]),
                          "+f"(acc[mi][ni][2]), "+f"(acc[mi][ni][3])
                        : "r"(a[mi][0]), "r"(a[mi][1]), "r"(a[mi][2]), "r"(a[mi][3]),
                          "r"(b0), "r"(b1));
                }
        }
    };

    // --- mainloop: 8 chunks, 3-stage ring, one sync per iter
    load_chunk(0);
    load_chunk(1);
    #pragma unroll 1
    for (int it = 0; it < 8; it++) {
        if (it < 7) asm volatile("cp.async.wait_group 1;\n" ::);
        else        asm volatile("cp.async.wait_group 0;\n" ::);
        __syncthreads();
        if (it + 2 < 8) load_chunk(it + 2);
        compute_chunk(it);
    }

    // --- epilogue: ex2 direct, shuffle reductions, DIRECT global atomics
    const bool posTile = ((bx - by) & 15) == 0;
    float rowp[2][2] = {{0.f, 0.f}, {0.f, 0.f}};
    float colp[8][2];
    #pragma unroll
    for (int ni = 0; ni < 8; ni++) { colp[ni][0] = 0.f; colp[ni][1] = 0.f; }

    #pragma unroll
    for (int mi = 0; mi < 2; mi++)
        #pragma unroll
        for (int ni = 0; ni < 8; ni++)
            #pragma unroll
            for (int e = 0; e < 4; e++) {
                float ev;
                asm("ex2.approx.f32 %0, %1;" : "=f"(ev) : "f"(acc[mi][ni][e]));
                rowp[mi][e >> 1] += ev;
                colp[ni][e & 1] += ev;
                if (posTile) {
                    int rl = wm * 32 + mi * 16 + (e >> 1) * 8 + (lane >> 2);
                    int cl = wn * 64 + ni * 8 + (lane & 3) * 2 + (e & 1);
                    if (rl == cl) {
                        int gr = rowBase + rl, gc = colBase + cl;
                        g_pos[((gr >> 11) * V_NUM + (gc >> 11)) * B_SZ + (gr & 2047)] =
                            acc[mi][ni][e] * LN2F;
                    }
                }
            }

    // row sums: quad reduce -> direct atomic (2 atomics/row across wn pair)
    #pragma unroll
    for (int mi = 0; mi < 2; mi++)
        #pragma unroll
        for (int rh = 0; rh < 2; rh++) {
            float s = rowp[mi][rh];
            s += __shfl_xor_sync(0xFFFFFFFFu, s, 1);
            s += __shfl_xor_sync(0xFFFFFFFFu, s, 2);
            if ((lane & 3) == 0)
                atomicAdd(&g_rowsum[rowBase + wm * 32 + mi * 16 + rh * 8 + (lane >> 2)], s);
        }
    // col sums (off-diag only): 8-lane reduce -> direct atomic (4/col)
    if (bx != by) {
        #pragma unroll
        for (int ni = 0; ni < 8; ni++)
            #pragma unroll
            for (int e01 = 0; e01 < 2; e01++) {
                float s = colp[ni][e01];
                s += __shfl_xor_sync(0xFFFFFFFFu, s, 4);
                s += __shfl_xor_sync(0xFFFFFFFFu, s, 8);
                s += __shfl_xor_sync(0xFFFFFFFFu, s, 16);
                if (lane < 4)
                    atomicAdd(&g_rowsum[colBase + wn * 64 + ni * 8 + lane * 2 + e01], s);
            }
    }
}

// ---------------------------------------------------------------------------
// Per-anchor loss from rowsum + extracted positives.
// ---------------------------------------------------------------------------
__global__ void loss_kernel(float* __restrict__ out) {
    int r = blockIdx.x * blockDim.x + threadIdx.x;
    int i = r >> 11, b = r & 2047;
    float p[V_NUM];
    #pragma unroll
    for (int j = 0; j < V_NUM; j++) {
        int lo = i < j ? i : j;
        int hi = i < j ? j : i;
        p[j] = g_pos[(lo * V_NUM + hi) * B_SZ + b];
    }
    float S = g_rowsum[r];
    #pragma unroll
    for (int j = 0; j < V_NUM; j++) S -= __expf(p[j]);
    float L = 0.0f;
    #pragma unroll
    for (int j = 0; j < V_NUM; j++)
        if (j != i) L += log1pf(S * __expf(-p[j]));
    L *= (1.0f / (float)B_SZ);
    #pragma unroll
    for (int o = 16; o > 0; o >>= 1) L += __shfl_xor_sync(0xFFFFFFFFu, L, o);
    __shared__ float ws[8];
    if ((threadIdx.x & 31) == 0) ws[threadIdx.x >> 5] = L;
    __syncthreads();
    if (threadIdx.x == 0) {
        float s = 0.0f;
        #pragma unroll
        for (int w = 0; w < 8; w++) s += ws[w];
        atomicAdd(out, s);
    }
}

// ---------------------------------------------------------------------------
extern "C" void kernel_launch(void* const* d_in, const int* in_sizes, int n_in,
                              void* d_out, int out_size) {
    const float* x = (const float*)d_in[0];
    float* out = (float*)d_out;

    cudaFuncSetAttribute(simexp_kernel,
                         cudaFuncAttributeMaxDynamicSharedMemorySize, SIMEXP_SMEM);

    normalize_kernel<<<N_ROWS / 8, 256>>>(x, out);
    simexp_kernel<<<NTILES, 256, SIMEXP_SMEM>>>();
    loss_kernel<<<N_ROWS / 256, 256>>>(out);
}